// round 3
// baseline (speedup 1.0000x reference)
#include <cuda_runtime.h>
#include <math.h>

// ---------------------------------------------------------------------------
// Problem constants
// ---------------------------------------------------------------------------
#define Bn   4
#define Sn   2048
#define Tn   2048
#define CIN  256     // CK = CV = CQ
#define HID  256
#define OUTC 256
#define Hn   4
#define CH   64      // per-head channels

// ---------------------------------------------------------------------------
// Scratch (static device allocations are the allowed scratch mechanism)
// ---------------------------------------------------------------------------
__device__ float g_k[Bn * HID * Sn];    // [b][c][s], c = h*64+ch
__device__ float g_v[Bn * HID * Sn];
__device__ float g_q[Bn * HID * Tn];
__device__ float g_attn[Bn * HID * Tn]; // attention output before final projection

// ---------------------------------------------------------------------------
// Kernel A: fused K/V/Q 1x1-conv projections.
// Y[b][o][l] = sum_i W[o][i] * X[b][i][l] + bias[o]
// Grid: (L/64, 256/64, B*3).  Block: 256 threads (16x16), 4x4 fragments.
// ---------------------------------------------------------------------------
__global__ void __launch_bounds__(256)
proj3_kernel(const float* __restrict__ keys,
             const float* __restrict__ values,
             const float* __restrict__ queries,
             const float* __restrict__ Wk, const float* __restrict__ bk,
             const float* __restrict__ Wv, const float* __restrict__ bv,
             const float* __restrict__ Wq, const float* __restrict__ bq)
{
    const int bz = blockIdx.z;
    const int b  = bz / 3;
    const int p  = bz % 3;

    const float* X;  const float* W;  const float* bias;  float* Y;
    if (p == 0)      { X = keys;    W = Wk; bias = bk; Y = g_k; }
    else if (p == 1) { X = values;  W = Wv; bias = bv; Y = g_v; }
    else             { X = queries; W = Wq; bias = bq; Y = g_q; }
    X += (size_t)b * CIN * Sn;
    Y += (size_t)b * HID * Sn;

    __shared__ __align__(16) float Ws[16][68];  // [k][o]  (transposed W tile)
    __shared__ __align__(16) float Xs[16][64];  // [k][l]

    const int tid = threadIdx.x;
    const int tx  = tid & 15;
    const int ty  = tid >> 4;
    const int otile = blockIdx.y * 64;
    const int ltile = blockIdx.x * 64;

    float acc[4][4] = {};

    for (int i0 = 0; i0 < CIN; i0 += 16) {
        // load W tile [64 o][16 k] -> Ws[k][o]
        {
            const int k  = tid & 15;
            const int ob = tid >> 4;
            #pragma unroll
            for (int r = 0; r < 4; r++)
                Ws[k][ob + r * 16] = W[(otile + ob + r * 16) * CIN + i0 + k];
        }
        // load X tile [16 k][64 l]
        {
            const int l  = tid & 63;
            const int kb = tid >> 6;
            #pragma unroll
            for (int r = 0; r < 4; r++)
                Xs[kb + r * 4][l] = X[(size_t)(i0 + kb + r * 4) * Sn + ltile + l];
        }
        __syncthreads();

        #pragma unroll
        for (int kk = 0; kk < 16; kk++) {
            float4 a4 = *(const float4*)&Ws[kk][ty * 4];
            float4 b4 = *(const float4*)&Xs[kk][tx * 4];
            float av[4] = {a4.x, a4.y, a4.z, a4.w};
            float bv4[4] = {b4.x, b4.y, b4.z, b4.w};
            #pragma unroll
            for (int i = 0; i < 4; i++)
                #pragma unroll
                for (int j = 0; j < 4; j++)
                    acc[i][j] += av[i] * bv4[j];
        }
        __syncthreads();
    }

    #pragma unroll
    for (int i = 0; i < 4; i++) {
        const int o = otile + ty * 4 + i;
        const float bb = bias[o];
        float4 v = make_float4(acc[i][0] + bb, acc[i][1] + bb,
                               acc[i][2] + bb, acc[i][3] + bb);
        *(float4*)&Y[(size_t)o * Sn + ltile + tx * 4] = v;
    }
}

// ---------------------------------------------------------------------------
// Kernel B: flash attention per (b, h, t-tile of 64).
// score[s,t] = (1/8) * sum_c K[c,s] Q[c,t];  masked (-1e30) if mask[b,s,0]<=0
// online softmax over s, O[c,t] = sum_s V[c,s] * softmax(score)[s,t]
// Block: 256 threads (16x16), 4x4 fragments for both GEMMs.
// ---------------------------------------------------------------------------
__global__ void __launch_bounds__(256)
attn_kernel(const float* __restrict__ mask)
{
    extern __shared__ __align__(16) float sm[];
    float* Qs   = sm;              // [64][68]  [c][t]
    float* Ks   = Qs + 64 * 68;    // [64][68]  [c][s]
    float* Vs   = Ks + 64 * 68;    // [64][68]  [s][c]
    float* Ps   = Vs + 64 * 68;    // [64][68]  [s][t]
    float* red  = Ps + 64 * 68;    // [16][64]
    float* cbuf = red + 16 * 64;   // [64]
    float* mskS = cbuf + 64;       // [64]

    const int tid = threadIdx.x;
    const int tx  = tid & 15;
    const int ty  = tid >> 4;
    const int t0  = blockIdx.x * 64;
    const int h   = blockIdx.y;
    const int b   = blockIdx.z;

    const float* qp = g_q + ((size_t)b * HID + h * CH) * Tn + t0;
    const float* kp = g_k + ((size_t)b * HID + h * CH) * Sn;
    const float* vp = g_v + ((size_t)b * HID + h * CH) * Sn;
    float*       op = g_attn + ((size_t)b * HID + h * CH) * Tn + t0;
    const float* mp = mask + (size_t)b * Sn * Tn;   // mask[b][s][0] = mp[s*Tn]

    // load Q tile [c][t]
    {
        const int t  = tid & 63;
        const int cb = tid >> 6;
        #pragma unroll
        for (int r = 0; r < 16; r++) {
            const int c = cb + r * 4;
            Qs[c * 68 + t] = qp[(size_t)c * Tn + t];
        }
    }

    float o_acc[4][4] = {};
    float run_m[4], run_l[4] = {};
    #pragma unroll
    for (int j = 0; j < 4; j++) run_m[j] = -INFINITY;

    __syncthreads();

    for (int s0 = 0; s0 < Sn; s0 += 64) {
        // load K tile [c][s] and V tile transposed [s][c]
        {
            const int s  = tid & 63;
            const int cb = tid >> 6;
            #pragma unroll
            for (int r = 0; r < 16; r++) {
                const int c = cb + r * 4;
                Ks[c * 68 + s] = kp[(size_t)c * Sn + s0 + s];
                Vs[s * 68 + c] = vp[(size_t)c * Sn + s0 + s];
            }
            if (tid < 64) mskS[tid] = mp[(size_t)(s0 + tid) * Tn];
        }
        __syncthreads();

        // GEMM1: p[s,t] = sum_c K[c,s] * Q[c,t]
        float p[4][4] = {};
        #pragma unroll 16
        for (int c = 0; c < 64; c++) {
            float4 a4 = *(const float4*)&Ks[c * 68 + ty * 4];
            float4 b4 = *(const float4*)&Qs[c * 68 + tx * 4];
            float av[4] = {a4.x, a4.y, a4.z, a4.w};
            float bv4[4] = {b4.x, b4.y, b4.z, b4.w};
            #pragma unroll
            for (int i = 0; i < 4; i++)
                #pragma unroll
                for (int j = 0; j < 4; j++)
                    p[i][j] += av[i] * bv4[j];
        }
        // scale + mask
        #pragma unroll
        for (int i = 0; i < 4; i++) {
            const bool masked = (mskS[ty * 4 + i] <= 0.0f);
            #pragma unroll
            for (int j = 0; j < 4; j++)
                p[i][j] = masked ? -1e30f : p[i][j] * 0.125f;
        }

        // column (over s) max: local then cross-warp via smem
        float lm[4];
        #pragma unroll
        for (int j = 0; j < 4; j++)
            lm[j] = fmaxf(fmaxf(p[0][j], p[1][j]), fmaxf(p[2][j], p[3][j]));
        *(float4*)&red[ty * 64 + tx * 4] = make_float4(lm[0], lm[1], lm[2], lm[3]);
        __syncthreads();
        if (tid < 64) {
            float m = red[tid];
            #pragma unroll
            for (int r = 1; r < 16; r++) m = fmaxf(m, red[r * 64 + tid]);
            cbuf[tid] = m;
        }
        __syncthreads();

        float alpha[4], ls[4];
        #pragma unroll
        for (int j = 0; j < 4; j++) {
            const float tm = cbuf[tx * 4 + j];
            const float nm = fmaxf(run_m[j], tm);
            alpha[j] = __expf(run_m[j] - nm);
            run_m[j] = nm;
            float ssum = 0.0f;
            #pragma unroll
            for (int i = 0; i < 4; i++) {
                p[i][j] = __expf(p[i][j] - nm);
                ssum += p[i][j];
            }
            ls[j] = ssum;
            #pragma unroll
            for (int i = 0; i < 4; i++) o_acc[i][j] *= alpha[j];
        }

        // stage P into smem + publish partial sums
        #pragma unroll
        for (int i = 0; i < 4; i++)
            *(float4*)&Ps[(ty * 4 + i) * 68 + tx * 4] =
                make_float4(p[i][0], p[i][1], p[i][2], p[i][3]);
        *(float4*)&red[ty * 64 + tx * 4] = make_float4(ls[0], ls[1], ls[2], ls[3]);
        __syncthreads();
        if (tid < 64) {
            float ssum = red[tid];
            #pragma unroll
            for (int r = 1; r < 16; r++) ssum += red[r * 64 + tid];
            cbuf[tid] = ssum;
        }
        __syncthreads();
        #pragma unroll
        for (int j = 0; j < 4; j++)
            run_l[j] = run_l[j] * alpha[j] + cbuf[tx * 4 + j];

        // GEMM2: O[c,t] += sum_s V[c,s] * P[s,t]
        #pragma unroll 16
        for (int s = 0; s < 64; s++) {
            float4 a4 = *(const float4*)&Vs[s * 68 + ty * 4];
            float4 b4 = *(const float4*)&Ps[s * 68 + tx * 4];
            float av[4] = {a4.x, a4.y, a4.z, a4.w};
            float pv[4] = {b4.x, b4.y, b4.z, b4.w};
            #pragma unroll
            for (int i = 0; i < 4; i++)
                #pragma unroll
                for (int j = 0; j < 4; j++)
                    o_acc[i][j] += av[i] * pv[j];
        }
        __syncthreads();
    }

    // epilogue: normalize and store
    float inv_l[4];
    #pragma unroll
    for (int j = 0; j < 4; j++) inv_l[j] = 1.0f / run_l[j];
    #pragma unroll
    for (int i = 0; i < 4; i++) {
        float4 v = make_float4(o_acc[i][0] * inv_l[0], o_acc[i][1] * inv_l[1],
                               o_acc[i][2] * inv_l[2], o_acc[i][3] * inv_l[3]);
        *(float4*)&op[(size_t)(ty * 4 + i) * Tn + tx * 4] = v;
    }
}

// ---------------------------------------------------------------------------
// Kernel C: output projection + mask gating, writes d_out.
// out[b][o][t] = (sum_i Wo[o][i] * attn[b][i][t] + bo[o]) * mask[b][0][t]
// ---------------------------------------------------------------------------
__global__ void __launch_bounds__(256)
outproj_kernel(const float* __restrict__ Wo, const float* __restrict__ bo,
               const float* __restrict__ mask, float* __restrict__ out)
{
    const int b = blockIdx.z;
    const float* X = g_attn + (size_t)b * HID * Tn;
    float*       Y = out    + (size_t)b * OUTC * Tn;

    __shared__ __align__(16) float Ws[16][68];
    __shared__ __align__(16) float Xs[16][64];

    const int tid = threadIdx.x;
    const int tx  = tid & 15;
    const int ty  = tid >> 4;
    const int otile = blockIdx.y * 64;
    const int ltile = blockIdx.x * 64;

    float acc[4][4] = {};

    for (int i0 = 0; i0 < HID; i0 += 16) {
        {
            const int k  = tid & 15;
            const int ob = tid >> 4;
            #pragma unroll
            for (int r = 0; r < 4; r++)
                Ws[k][ob + r * 16] = Wo[(otile + ob + r * 16) * HID + i0 + k];
        }
        {
            const int l  = tid & 63;
            const int kb = tid >> 6;
            #pragma unroll
            for (int r = 0; r < 4; r++)
                Xs[kb + r * 4][l] = X[(size_t)(i0 + kb + r * 4) * Tn + ltile + l];
        }
        __syncthreads();

        #pragma unroll
        for (int kk = 0; kk < 16; kk++) {
            float4 a4 = *(const float4*)&Ws[kk][ty * 4];
            float4 b4 = *(const float4*)&Xs[kk][tx * 4];
            float av[4] = {a4.x, a4.y, a4.z, a4.w};
            float bv4[4] = {b4.x, b4.y, b4.z, b4.w};
            #pragma unroll
            for (int i = 0; i < 4; i++)
                #pragma unroll
                for (int j = 0; j < 4; j++)
                    acc[i][j] += av[i] * bv4[j];
        }
        __syncthreads();
    }

    // mask[b][0][t]
    const float4 mv = *(const float4*)&mask[(size_t)b * Sn * Tn + ltile + tx * 4];
    const float mvv[4] = {mv.x, mv.y, mv.z, mv.w};

    #pragma unroll
    for (int i = 0; i < 4; i++) {
        const int o = otile + ty * 4 + i;
        const float bb = bo[o];
        float4 v = make_float4((acc[i][0] + bb) * mvv[0],
                               (acc[i][1] + bb) * mvv[1],
                               (acc[i][2] + bb) * mvv[2],
                               (acc[i][3] + bb) * mvv[3]);
        *(float4*)&Y[(size_t)o * Tn + ltile + tx * 4] = v;
    }
}

// ---------------------------------------------------------------------------
// Launch
// ---------------------------------------------------------------------------
extern "C" void kernel_launch(void* const* d_in, const int* in_sizes, int n_in,
                              void* d_out, int out_size)
{
    const float* keys    = (const float*)d_in[0];
    const float* values  = (const float*)d_in[1];
    const float* queries = (const float*)d_in[2];
    const float* mask    = (const float*)d_in[3];
    const float* Wk = (const float*)d_in[4];
    const float* bk = (const float*)d_in[5];
    const float* Wv = (const float*)d_in[6];
    const float* bv = (const float*)d_in[7];
    const float* Wq = (const float*)d_in[8];
    const float* bq = (const float*)d_in[9];
    const float* Wo = (const float*)d_in[10];
    const float* bo = (const float*)d_in[11];
    float* out = (float*)d_out;

    // attn_kernel needs >48KB dynamic smem
    const int smem_bytes = (4 * 64 * 68 + 16 * 64 + 64 + 64) * (int)sizeof(float);
    cudaFuncSetAttribute(attn_kernel,
                         cudaFuncAttributeMaxDynamicSharedMemorySize, smem_bytes);

    proj3_kernel<<<dim3(Sn / 64, HID / 64, Bn * 3), 256>>>(
        keys, values, queries, Wk, bk, Wv, bv, Wq, bq);

    attn_kernel<<<dim3(Tn / 64, Hn, Bn), 256, smem_bytes>>>(mask);

    outproj_kernel<<<dim3(Tn / 64, OUTC / 64, Bn), 256>>>(Wo, bo, mask, out);
}

// round 4
// speedup vs baseline: 1.0001x; 1.0001x over previous
#include <cuda_runtime.h>
#include <math.h>

// ---------------------------------------------------------------------------
// Problem constants
// ---------------------------------------------------------------------------
#define Bn   4
#define Sn   2048
#define Tn   2048
#define CIN  256     // CK = CV = CQ
#define HID  256
#define OUTC 256
#define Hn   4
#define CH   64      // per-head channels

// ---------------------------------------------------------------------------
// Scratch (static device allocations are the allowed scratch mechanism)
// ---------------------------------------------------------------------------
__device__ float g_k[Bn * HID * Sn];    // [b][c][s], c = h*64+ch
__device__ float g_v[Bn * HID * Sn];
__device__ float g_q[Bn * HID * Tn];
__device__ float g_attn[Bn * HID * Tn]; // attention output before final projection

// ---------------------------------------------------------------------------
// Kernel A: fused K/V/Q 1x1-conv projections.
// Y[b][o][l] = sum_i W[o][i] * X[b][i][l] + bias[o]
// Grid: (L/64, 256/64, B*3).  Block: 256 threads (16x16), 4x4 fragments.
// ---------------------------------------------------------------------------
__global__ void __launch_bounds__(256)
proj3_kernel(const float* __restrict__ keys,
             const float* __restrict__ values,
             const float* __restrict__ queries,
             const float* __restrict__ Wk, const float* __restrict__ bk,
             const float* __restrict__ Wv, const float* __restrict__ bv,
             const float* __restrict__ Wq, const float* __restrict__ bq)
{
    const int bz = blockIdx.z;
    const int b  = bz / 3;
    const int p  = bz % 3;

    const float* X;  const float* W;  const float* bias;  float* Y;
    if (p == 0)      { X = keys;    W = Wk; bias = bk; Y = g_k; }
    else if (p == 1) { X = values;  W = Wv; bias = bv; Y = g_v; }
    else             { X = queries; W = Wq; bias = bq; Y = g_q; }
    X += (size_t)b * CIN * Sn;
    Y += (size_t)b * HID * Sn;

    __shared__ __align__(16) float Ws[16][68];  // [k][o]  (transposed W tile)
    __shared__ __align__(16) float Xs[16][64];  // [k][l]

    const int tid = threadIdx.x;
    const int tx  = tid & 15;
    const int ty  = tid >> 4;
    const int otile = blockIdx.y * 64;
    const int ltile = blockIdx.x * 64;

    float acc[4][4] = {};

    for (int i0 = 0; i0 < CIN; i0 += 16) {
        // load W tile [64 o][16 k] -> Ws[k][o]
        {
            const int k  = tid & 15;
            const int ob = tid >> 4;
            #pragma unroll
            for (int r = 0; r < 4; r++)
                Ws[k][ob + r * 16] = W[(otile + ob + r * 16) * CIN + i0 + k];
        }
        // load X tile [16 k][64 l]
        {
            const int l  = tid & 63;
            const int kb = tid >> 6;
            #pragma unroll
            for (int r = 0; r < 4; r++)
                Xs[kb + r * 4][l] = X[(size_t)(i0 + kb + r * 4) * Sn + ltile + l];
        }
        __syncthreads();

        #pragma unroll
        for (int kk = 0; kk < 16; kk++) {
            float4 a4 = *(const float4*)&Ws[kk][ty * 4];
            float4 b4 = *(const float4*)&Xs[kk][tx * 4];
            float av[4] = {a4.x, a4.y, a4.z, a4.w};
            float bv4[4] = {b4.x, b4.y, b4.z, b4.w};
            #pragma unroll
            for (int i = 0; i < 4; i++)
                #pragma unroll
                for (int j = 0; j < 4; j++)
                    acc[i][j] += av[i] * bv4[j];
        }
        __syncthreads();
    }

    #pragma unroll
    for (int i = 0; i < 4; i++) {
        const int o = otile + ty * 4 + i;
        const float bb = bias[o];
        float4 v = make_float4(acc[i][0] + bb, acc[i][1] + bb,
                               acc[i][2] + bb, acc[i][3] + bb);
        *(float4*)&Y[(size_t)o * Sn + ltile + tx * 4] = v;
    }
}

// ---------------------------------------------------------------------------
// Kernel B: flash attention per (b, h, t-tile of 64).
// score[s,t] = (1/8) * sum_c K[c,s] Q[c,t];  masked (-1e30) if mask[b,s,0]<=0
// online softmax over s, O[c,t] = sum_s V[c,s] * softmax(score)[s,t]
// Block: 256 threads (16x16), 4x4 fragments for both GEMMs.
// ---------------------------------------------------------------------------
__global__ void __launch_bounds__(256)
attn_kernel(const float* __restrict__ mask)
{
    extern __shared__ __align__(16) float sm[];
    float* Qs   = sm;              // [64][68]  [c][t]
    float* Ks   = Qs + 64 * 68;    // [64][68]  [c][s]
    float* Vs   = Ks + 64 * 68;    // [64][68]  [s][c]
    float* Ps   = Vs + 64 * 68;    // [64][68]  [s][t]
    float* red  = Ps + 64 * 68;    // [16][64]
    float* cbuf = red + 16 * 64;   // [64]
    float* mskS = cbuf + 64;       // [64]

    const int tid = threadIdx.x;
    const int tx  = tid & 15;
    const int ty  = tid >> 4;
    const int t0  = blockIdx.x * 64;
    const int h   = blockIdx.y;
    const int b   = blockIdx.z;

    const float* qp = g_q + ((size_t)b * HID + h * CH) * Tn + t0;
    const float* kp = g_k + ((size_t)b * HID + h * CH) * Sn;
    const float* vp = g_v + ((size_t)b * HID + h * CH) * Sn;
    float*       op = g_attn + ((size_t)b * HID + h * CH) * Tn + t0;
    const float* mp = mask + (size_t)b * Sn * Tn;   // mask[b][s][0] = mp[s*Tn]

    // load Q tile [c][t]
    {
        const int t  = tid & 63;
        const int cb = tid >> 6;
        #pragma unroll
        for (int r = 0; r < 16; r++) {
            const int c = cb + r * 4;
            Qs[c * 68 + t] = qp[(size_t)c * Tn + t];
        }
    }

    float o_acc[4][4] = {};
    float run_m[4], run_l[4] = {};
    #pragma unroll
    for (int j = 0; j < 4; j++) run_m[j] = -INFINITY;

    __syncthreads();

    for (int s0 = 0; s0 < Sn; s0 += 64) {
        // load K tile [c][s] and V tile transposed [s][c]
        {
            const int s  = tid & 63;
            const int cb = tid >> 6;
            #pragma unroll
            for (int r = 0; r < 16; r++) {
                const int c = cb + r * 4;
                Ks[c * 68 + s] = kp[(size_t)c * Sn + s0 + s];
                Vs[s * 68 + c] = vp[(size_t)c * Sn + s0 + s];
            }
            if (tid < 64) mskS[tid] = mp[(size_t)(s0 + tid) * Tn];
        }
        __syncthreads();

        // GEMM1: p[s,t] = sum_c K[c,s] * Q[c,t]
        float p[4][4] = {};
        #pragma unroll 16
        for (int c = 0; c < 64; c++) {
            float4 a4 = *(const float4*)&Ks[c * 68 + ty * 4];
            float4 b4 = *(const float4*)&Qs[c * 68 + tx * 4];
            float av[4] = {a4.x, a4.y, a4.z, a4.w};
            float bv4[4] = {b4.x, b4.y, b4.z, b4.w};
            #pragma unroll
            for (int i = 0; i < 4; i++)
                #pragma unroll
                for (int j = 0; j < 4; j++)
                    p[i][j] += av[i] * bv4[j];
        }
        // scale + mask
        #pragma unroll
        for (int i = 0; i < 4; i++) {
            const bool masked = (mskS[ty * 4 + i] <= 0.0f);
            #pragma unroll
            for (int j = 0; j < 4; j++)
                p[i][j] = masked ? -1e30f : p[i][j] * 0.125f;
        }

        // column (over s) max: local then cross-warp via smem
        float lm[4];
        #pragma unroll
        for (int j = 0; j < 4; j++)
            lm[j] = fmaxf(fmaxf(p[0][j], p[1][j]), fmaxf(p[2][j], p[3][j]));
        *(float4*)&red[ty * 64 + tx * 4] = make_float4(lm[0], lm[1], lm[2], lm[3]);
        __syncthreads();
        if (tid < 64) {
            float m = red[tid];
            #pragma unroll
            for (int r = 1; r < 16; r++) m = fmaxf(m, red[r * 64 + tid]);
            cbuf[tid] = m;
        }
        __syncthreads();

        float alpha[4], ls[4];
        #pragma unroll
        for (int j = 0; j < 4; j++) {
            const float tm = cbuf[tx * 4 + j];
            const float nm = fmaxf(run_m[j], tm);
            alpha[j] = __expf(run_m[j] - nm);
            run_m[j] = nm;
            float ssum = 0.0f;
            #pragma unroll
            for (int i = 0; i < 4; i++) {
                p[i][j] = __expf(p[i][j] - nm);
                ssum += p[i][j];
            }
            ls[j] = ssum;
            #pragma unroll
            for (int i = 0; i < 4; i++) o_acc[i][j] *= alpha[j];
        }

        // stage P into smem + publish partial sums
        #pragma unroll
        for (int i = 0; i < 4; i++)
            *(float4*)&Ps[(ty * 4 + i) * 68 + tx * 4] =
                make_float4(p[i][0], p[i][1], p[i][2], p[i][3]);
        *(float4*)&red[ty * 64 + tx * 4] = make_float4(ls[0], ls[1], ls[2], ls[3]);
        __syncthreads();
        if (tid < 64) {
            float ssum = red[tid];
            #pragma unroll
            for (int r = 1; r < 16; r++) ssum += red[r * 64 + tid];
            cbuf[tid] = ssum;
        }
        __syncthreads();
        #pragma unroll
        for (int j = 0; j < 4; j++)
            run_l[j] = run_l[j] * alpha[j] + cbuf[tx * 4 + j];

        // GEMM2: O[c,t] += sum_s V[c,s] * P[s,t]
        #pragma unroll 16
        for (int s = 0; s < 64; s++) {
            float4 a4 = *(const float4*)&Vs[s * 68 + ty * 4];
            float4 b4 = *(const float4*)&Ps[s * 68 + tx * 4];
            float av[4] = {a4.x, a4.y, a4.z, a4.w};
            float pv[4] = {b4.x, b4.y, b4.z, b4.w};
            #pragma unroll
            for (int i = 0; i < 4; i++)
                #pragma unroll
                for (int j = 0; j < 4; j++)
                    o_acc[i][j] += av[i] * pv[j];
        }
        __syncthreads();
    }

    // epilogue: normalize and store
    float inv_l[4];
    #pragma unroll
    for (int j = 0; j < 4; j++) inv_l[j] = 1.0f / run_l[j];
    #pragma unroll
    for (int i = 0; i < 4; i++) {
        float4 v = make_float4(o_acc[i][0] * inv_l[0], o_acc[i][1] * inv_l[1],
                               o_acc[i][2] * inv_l[2], o_acc[i][3] * inv_l[3]);
        *(float4*)&op[(size_t)(ty * 4 + i) * Tn + tx * 4] = v;
    }
}

// ---------------------------------------------------------------------------
// Kernel C: output projection + mask gating, writes d_out.
// out[b][o][t] = (sum_i Wo[o][i] * attn[b][i][t] + bo[o]) * mask[b][0][t]
// ---------------------------------------------------------------------------
__global__ void __launch_bounds__(256)
outproj_kernel(const float* __restrict__ Wo, const float* __restrict__ bo,
               const float* __restrict__ mask, float* __restrict__ out)
{
    const int b = blockIdx.z;
    const float* X = g_attn + (size_t)b * HID * Tn;
    float*       Y = out    + (size_t)b * OUTC * Tn;

    __shared__ __align__(16) float Ws[16][68];
    __shared__ __align__(16) float Xs[16][64];

    const int tid = threadIdx.x;
    const int tx  = tid & 15;
    const int ty  = tid >> 4;
    const int otile = blockIdx.y * 64;
    const int ltile = blockIdx.x * 64;

    float acc[4][4] = {};

    for (int i0 = 0; i0 < HID; i0 += 16) {
        {
            const int k  = tid & 15;
            const int ob = tid >> 4;
            #pragma unroll
            for (int r = 0; r < 4; r++)
                Ws[k][ob + r * 16] = Wo[(otile + ob + r * 16) * HID + i0 + k];
        }
        {
            const int l  = tid & 63;
            const int kb = tid >> 6;
            #pragma unroll
            for (int r = 0; r < 4; r++)
                Xs[kb + r * 4][l] = X[(size_t)(i0 + kb + r * 4) * Tn + ltile + l];
        }
        __syncthreads();

        #pragma unroll
        for (int kk = 0; kk < 16; kk++) {
            float4 a4 = *(const float4*)&Ws[kk][ty * 4];
            float4 b4 = *(const float4*)&Xs[kk][tx * 4];
            float av[4] = {a4.x, a4.y, a4.z, a4.w};
            float bv4[4] = {b4.x, b4.y, b4.z, b4.w};
            #pragma unroll
            for (int i = 0; i < 4; i++)
                #pragma unroll
                for (int j = 0; j < 4; j++)
                    acc[i][j] += av[i] * bv4[j];
        }
        __syncthreads();
    }

    // mask[b][0][t]
    const float4 mv = *(const float4*)&mask[(size_t)b * Sn * Tn + ltile + tx * 4];
    const float mvv[4] = {mv.x, mv.y, mv.z, mv.w};

    #pragma unroll
    for (int i = 0; i < 4; i++) {
        const int o = otile + ty * 4 + i;
        const float bb = bo[o];
        float4 v = make_float4((acc[i][0] + bb) * mvv[0],
                               (acc[i][1] + bb) * mvv[1],
                               (acc[i][2] + bb) * mvv[2],
                               (acc[i][3] + bb) * mvv[3]);
        *(float4*)&Y[(size_t)o * Tn + ltile + tx * 4] = v;
    }
}

// ---------------------------------------------------------------------------
// Launch
// ---------------------------------------------------------------------------
extern "C" void kernel_launch(void* const* d_in, const int* in_sizes, int n_in,
                              void* d_out, int out_size)
{
    const float* keys    = (const float*)d_in[0];
    const float* values  = (const float*)d_in[1];
    const float* queries = (const float*)d_in[2];
    const float* mask    = (const float*)d_in[3];
    const float* Wk = (const float*)d_in[4];
    const float* bk = (const float*)d_in[5];
    const float* Wv = (const float*)d_in[6];
    const float* bv = (const float*)d_in[7];
    const float* Wq = (const float*)d_in[8];
    const float* bq = (const float*)d_in[9];
    const float* Wo = (const float*)d_in[10];
    const float* bo = (const float*)d_in[11];
    float* out = (float*)d_out;

    // attn_kernel needs >48KB dynamic smem
    const int smem_bytes = (4 * 64 * 68 + 16 * 64 + 64 + 64) * (int)sizeof(float);
    cudaFuncSetAttribute(attn_kernel,
                         cudaFuncAttributeMaxDynamicSharedMemorySize, smem_bytes);

    proj3_kernel<<<dim3(Sn / 64, HID / 64, Bn * 3), 256>>>(
        keys, values, queries, Wk, bk, Wv, bv, Wq, bq);

    attn_kernel<<<dim3(Tn / 64, Hn, Bn), 256, smem_bytes>>>(mask);

    outproj_kernel<<<dim3(Tn / 64, OUTC / 64, Bn), 256>>>(Wo, bo, mask, out);
}